// round 3
// baseline (speedup 1.0000x reference)
#include <cuda_runtime.h>

typedef unsigned long long u64;

// Problem constants
#define NPTS   16384           // N*P
#define KNB    16              // K neighbors
#define C_IN   128
#define C_MID  64
#define C_OUT  256
#define C_CAT  192             // C_MID + C_IN
#define KK     256             // K*K
#define CD     384             // C_CAT * DM
#define EPSBN  1e-5f

// ---------------- device scratch (no allocations allowed) ----------------
__device__ float g_pl  [NPTS * KNB * 3];     // pts_local
__device__ float g_lift[NPTS * KNB * C_MID]; // lifted features
__device__ float g_x   [NPTS * KK];          // X transform
__device__ float g_dw  [NPTS * CD];          // depthwise output
__device__ float g_pre [NPTS * C_OUT];       // pre-BN relu output
__device__ float g_cvt [48 * KK];            // cv_w transposed
__device__ float g_pwt [CD * C_OUT];         // pw_w transposed
__device__ float g_part[256 * 2 * C_OUT];    // per-block BN partials
__device__ float g_stats[2 * C_OUT];         // mean, inv_std

// ---------------- packed f32x2 helpers -----------------------------------
__device__ __forceinline__ void fma2(u64& d, u64 a, u64 b) {
    asm("fma.rn.f32x2 %0, %1, %2, %0;" : "+l"(d) : "l"(a), "l"(b));
}
__device__ __forceinline__ u64 dupf(float v) {
    unsigned u = __float_as_uint(v);
    return ((u64)u << 32) | (u64)u;
}
__device__ __forceinline__ u64 pack2(float lo, float hi) {
    u64 r;
    asm("mov.b64 %0, {%1, %2};" : "=l"(r) : "r"(__float_as_uint(lo)), "r"(__float_as_uint(hi)));
    return r;
}
__device__ __forceinline__ float lo32(u64 v) { return __uint_as_float((unsigned)v); }
__device__ __forceinline__ float hi32(u64 v) { return __uint_as_float((unsigned)(v >> 32)); }

// ---------------- k0: transpose small weights ----------------------------
__global__ void k0_prep(const float* __restrict__ cv_w,
                        const float* __restrict__ pw_w) {
    int tot = 48 * KK + CD * C_OUT;
    for (int idx = blockIdx.x * blockDim.x + threadIdx.x; idx < tot;
         idx += gridDim.x * blockDim.x) {
        if (idx < 48 * KK) {
            int j = idx >> 8, o = idx & 255;
            int k = j / 3, d = j - k * 3;
            g_cvt[idx] = cv_w[o * 48 + d * 16 + k];
        } else {
            int i = idx - 48 * KK;
            int j = i >> 8, o = i & 255;
            g_pwt[i] = pw_w[o * CD + j];
        }
    }
}

// ---------------- k1: pts_local + lift MLP -------------------------------
// 4 points / block, 128 threads. 64 rows. Stage2: f32x2, tile 4r x 8c.
__global__ void k1_lift(const float* __restrict__ rep,
                        const float* __restrict__ pts,
                        const float* __restrict__ w1, const float* __restrict__ b1,
                        const float* __restrict__ w2, const float* __restrict__ b2) {
    __shared__ float s_pl[4 * KNB * 3];           // 192
    __shared__ u64 s_h[64 * 65];                  // 33.3 KB (pad 65 vs banks)
    int tid = threadIdx.x;
    int base = blockIdx.x * 192;

    for (int idx = tid; idx < 192; idx += 128) {
        int p = blockIdx.x * 4 + idx / 48;
        int d = idx % 3;
        float v = pts[base + idx] - rep[p * 3 + d];
        s_pl[idx] = v;
        g_pl[base + idx] = v;
    }
    __syncthreads();

    // h = relu(pl @ w1 + b1), stored duplicated
    for (int e = tid; e < 64 * 64; e += 128) {
        int row = e >> 6, o = e & 63;
        float v = __ldg(b1 + o);
        v += s_pl[row * 3 + 0] * __ldg(w1 + o);
        v += s_pl[row * 3 + 1] * __ldg(w1 + 64 + o);
        v += s_pl[row * 3 + 2] * __ldg(w1 + 128 + o);
        s_h[row * 65 + o] = dupf(fmaxf(v, 0.f));
    }
    __syncthreads();

    int cg = tid & 7, rg = tid >> 3;
    int r0 = rg * 4, c0 = cg * 8;
    u64 acc[4][4];
    {
        ulonglong2 bb0 = *(const ulonglong2*)(b2 + c0);
        ulonglong2 bb1 = *(const ulonglong2*)(b2 + c0 + 4);
#pragma unroll
        for (int r = 0; r < 4; r++) {
            acc[r][0] = bb0.x; acc[r][1] = bb0.y;
            acc[r][2] = bb1.x; acc[r][3] = bb1.y;
        }
    }
#pragma unroll 4
    for (int j = 0; j < 64; j++) {
        ulonglong2 w0 = *(const ulonglong2*)(w2 + j * 64 + c0);
        ulonglong2 w1v = *(const ulonglong2*)(w2 + j * 64 + c0 + 4);
#pragma unroll
        for (int r = 0; r < 4; r++) {
            u64 a = s_h[(r0 + r) * 65 + j];
            fma2(acc[r][0], a, w0.x);  fma2(acc[r][1], a, w0.y);
            fma2(acc[r][2], a, w1v.x); fma2(acc[r][3], a, w1v.y);
        }
    }
    int growbase = blockIdx.x * 64;
#pragma unroll
    for (int r = 0; r < 4; r++) {
        float* op = g_lift + (growbase + r0 + r) * 64 + c0;
        float4 v0, v1;
        v0.x = fmaxf(lo32(acc[r][0]), 0.f); v0.y = fmaxf(hi32(acc[r][0]), 0.f);
        v0.z = fmaxf(lo32(acc[r][1]), 0.f); v0.w = fmaxf(hi32(acc[r][1]), 0.f);
        v1.x = fmaxf(lo32(acc[r][2]), 0.f); v1.y = fmaxf(hi32(acc[r][2]), 0.f);
        v1.z = fmaxf(lo32(acc[r][3]), 0.f); v1.w = fmaxf(hi32(acc[r][3]), 0.f);
        *(float4*)op = v0;
        *(float4*)(op + 4) = v1;
    }
}

// ---------------- k2: fused X-transform, f32x2, 8 pts/block --------------
// 128 threads, tile 2 rows x 8 cols (4 col-pairs). smem 35 KB.
#define K2P 8

template<int KD, bool RELU, bool TOGLOBAL>
__device__ __forceinline__ void k2_stage(const u64* sA,
                                         const float* __restrict__ W,
                                         const float* __restrict__ bias,
                                         u64* sOut, float* gOut,
                                         int r0, int c0) {
    u64 acc[2][4];
    {
        ulonglong2 bb0 = *(const ulonglong2*)(bias + c0);
        ulonglong2 bb1 = *(const ulonglong2*)(bias + c0 + 4);
#pragma unroll
        for (int r = 0; r < 2; r++) {
            acc[r][0] = bb0.x; acc[r][1] = bb0.y;
            acc[r][2] = bb1.x; acc[r][3] = bb1.y;
        }
    }
#pragma unroll 4
    for (int j = 0; j < KD; j++) {
        ulonglong2 w0 = *(const ulonglong2*)(W + j * 256 + c0);
        ulonglong2 w1 = *(const ulonglong2*)(W + j * 256 + c0 + 4);
        u64 a0 = sA[(r0 + 0) * KD + j];
        u64 a1 = sA[(r0 + 1) * KD + j];
        fma2(acc[0][0], a0, w0.x); fma2(acc[0][1], a0, w0.y);
        fma2(acc[0][2], a0, w1.x); fma2(acc[0][3], a0, w1.y);
        fma2(acc[1][0], a1, w0.x); fma2(acc[1][1], a1, w0.y);
        fma2(acc[1][2], a1, w1.x); fma2(acc[1][3], a1, w1.y);
    }
#pragma unroll
    for (int r = 0; r < 2; r++) {
        float v[8];
#pragma unroll
        for (int t = 0; t < 4; t++) { v[2*t] = lo32(acc[r][t]); v[2*t+1] = hi32(acc[r][t]); }
        if (RELU) {
#pragma unroll
            for (int t = 0; t < 8; t++) v[t] = fmaxf(v[t], 0.f);
        }
        if (TOGLOBAL) {
            float* op = gOut + (r0 + r) * 256 + c0;
            *(float4*)op = make_float4(v[0], v[1], v[2], v[3]);
            *(float4*)(op + 4) = make_float4(v[4], v[5], v[6], v[7]);
        } else {
            u64* op = sOut + (r0 + r) * 256 + c0;
#pragma unroll
            for (int t = 0; t < 8; t++) op[t] = dupf(v[t]);
        }
    }
}

__global__ void k2_xtrans(const float* __restrict__ cv_b,
                          const float* __restrict__ x1w, const float* __restrict__ x1b,
                          const float* __restrict__ x2w, const float* __restrict__ x2b) {
    __shared__ u64 s_a[K2P * 48];        // 3 KB
    __shared__ u64 s_b0[K2P * 256];      // 16 KB
    __shared__ u64 s_b1[K2P * 256];      // 16 KB
    int tid = threadIdx.x;
    int pbase = blockIdx.x * K2P;

    for (int idx = tid; idx < K2P * 48; idx += 128)
        s_a[idx] = dupf(g_pl[pbase * 48 + idx]);
    __syncthreads();

    int cg = tid & 31, rg = tid >> 5;   // 4 rgs (2 rows), 32 cgs (8 cols)
    int r0 = rg * 2, c0 = cg * 8;

    k2_stage<48, true, false>(s_a, g_cvt, cv_b, s_b0, (float*)0, r0, c0);
    __syncthreads();
    k2_stage<256, true, false>(s_b0, x1w, x1b, s_b1, (float*)0, r0, c0);
    __syncthreads();
    k2_stage<256, false, true>(s_b1, x2w, x2b, (u64*)0, g_x + pbase * KK, r0, c0);
}

// ---------------- k3: apply 16x16 X + depthwise conv, f32x2 --------------
// 8 points / block, 192 threads (one per concat channel).
__global__ void k3_mid(const float* __restrict__ fts,
                       const float* __restrict__ dww,
                       const float* __restrict__ dwb) {
    __shared__ u64 s_wt2[16 * 193];               // 24.7 KB padded transpose
    __shared__ __align__(16) float s_X[KK];
    int tid = threadIdx.x;

    // stage packed dw weights: dww [c][m][k] -> u64 pairs [c][i], i = m*8+q
    const u64* dw2 = (const u64*)dww;
    for (int idx = tid; idx < 192 * 16; idx += 192) {
        int c = idx >> 4, i = idx & 15;
        s_wt2[i * 193 + c] = dw2[idx];
    }
    __syncthreads();
    u64 wreg2[16];
#pragma unroll
    for (int i = 0; i < 16; i++) wreg2[i] = s_wt2[i * 193 + tid];
    float b0 = __ldg(dwb + 2 * tid), b1 = __ldg(dwb + 2 * tid + 1);

    for (int pp = 0; pp < 8; pp++) {
        int p = blockIdx.x * 8 + pp;
        __syncthreads();
        for (int i = tid; i < KK; i += 192) s_X[i] = g_x[p * KK + i];
        __syncthreads();

        u64 fcat2[8];
        if (tid < C_MID) {
#pragma unroll
            for (int jp = 0; jp < 8; jp++) {
                float f0 = g_lift[(p * KNB + 2 * jp) * C_MID + tid];
                float f1 = g_lift[(p * KNB + 2 * jp + 1) * C_MID + tid];
                fcat2[jp] = pack2(f0, f1);
            }
        } else {
            int cc = tid - C_MID;
#pragma unroll
            for (int jp = 0; jp < 8; jp++) {
                float f0 = __ldg(fts + (p * KNB + 2 * jp) * C_IN + cc);
                float f1 = __ldg(fts + (p * KNB + 2 * jp + 1) * C_IN + cc);
                fcat2[jp] = pack2(f0, f1);
            }
        }

        float fx[KNB];
        const ulonglong2* X2 = (const ulonglong2*)s_X;
#pragma unroll
        for (int i = 0; i < KNB; i++) {
            u64 acc = 0;
#pragma unroll
            for (int q2 = 0; q2 < 4; q2++) {
                ulonglong2 x = X2[i * 4 + q2];
                fma2(acc, fcat2[2 * q2], x.x);
                fma2(acc, fcat2[2 * q2 + 1], x.y);
            }
            fx[i] = lo32(acc) + hi32(acc);
        }
        u64 a0 = 0, a1 = 0;
#pragma unroll
        for (int q = 0; q < 8; q++) {
            u64 f2 = pack2(fx[2 * q], fx[2 * q + 1]);
            fma2(a0, f2, wreg2[q]);
            fma2(a1, f2, wreg2[8 + q]);
        }
        float o0 = b0 + lo32(a0) + hi32(a0);
        float o1 = b1 + lo32(a1) + hi32(a1);
        *(float2*)(g_dw + p * CD + 2 * tid) = make_float2(o0, o1);
    }
}

// ---------------- k4: pointwise GEMM + relu + BN partials, f32x2 ---------
// 64 rows/block, 256 threads, tile 8r x 8c (4 col-pairs). smem 32 KB (union).
__global__ void k4_pw() {
    __shared__ u64 s_a[64 * 64];                   // 32 KB, reused as s_red
    int tid = threadIdx.x;
    int cg = tid & 31, rg = tid >> 5;
    int r0 = rg * 8, c0 = cg * 8;
    int rowbase = blockIdx.x * 64;

    u64 acc[8][4];
#pragma unroll
    for (int r = 0; r < 8; r++)
#pragma unroll
        for (int t = 0; t < 4; t++) acc[r][t] = 0ull;

    for (int jc = 0; jc < 6; jc++) {
        __syncthreads();
        for (int idx = tid; idx < 4096; idx += 256) {
            int r = idx >> 6, j = idx & 63;
            s_a[idx] = dupf(g_dw[(rowbase + r) * CD + jc * 64 + j]);
        }
        __syncthreads();
#pragma unroll 4
        for (int j = 0; j < 64; j++) {
            const float* wp = g_pwt + (jc * 64 + j) * 256 + c0;
            ulonglong2 w0 = *(const ulonglong2*)wp;
            ulonglong2 w1 = *(const ulonglong2*)(wp + 4);
#pragma unroll
            for (int r = 0; r < 8; r++) {
                u64 a = s_a[(r0 + r) * 64 + j];
                fma2(acc[r][0], a, w0.x); fma2(acc[r][1], a, w0.y);
                fma2(acc[r][2], a, w1.x); fma2(acc[r][3], a, w1.y);
            }
        }
    }

    // relu + store + BN partials
    float csum[8], csq[8];
#pragma unroll
    for (int c = 0; c < 8; c++) { csum[c] = 0.f; csq[c] = 0.f; }
#pragma unroll
    for (int r = 0; r < 8; r++) {
        float v[8];
#pragma unroll
        for (int t = 0; t < 4; t++) {
            v[2*t] = fmaxf(lo32(acc[r][t]), 0.f);
            v[2*t+1] = fmaxf(hi32(acc[r][t]), 0.f);
        }
#pragma unroll
        for (int c = 0; c < 8; c++) { csum[c] += v[c]; csq[c] += v[c] * v[c]; }
        float* op = g_pre + (rowbase + r0 + r) * C_OUT + c0;
        *(float4*)op = make_float4(v[0], v[1], v[2], v[3]);
        *(float4*)(op + 4) = make_float4(v[4], v[5], v[6], v[7]);
    }
    __syncthreads();
    float* s_red = (float*)s_a;                    // reuse 32 KB (need 16 KB)
#pragma unroll
    for (int c = 0; c < 8; c++) {
        s_red[rg * C_OUT + c0 + c] = csum[c];
        s_red[8 * C_OUT + rg * C_OUT + c0 + c] = csq[c];
    }
    __syncthreads();
    float s = 0.f, s2 = 0.f;
#pragma unroll
    for (int g = 0; g < 8; g++) {
        s  += s_red[g * C_OUT + tid];
        s2 += s_red[8 * C_OUT + g * C_OUT + tid];
    }
    g_part[blockIdx.x * 512 + tid] = s;
    g_part[blockIdx.x * 512 + 256 + tid] = s2;
}

// ---------------- k5: final BN stats -------------------------------------
__global__ void k5_stats() {
    int o = threadIdx.x;
    float s = 0.f, s2 = 0.f;
    for (int b = 0; b < 256; b++) {
        s  += g_part[b * 512 + o];
        s2 += g_part[b * 512 + 256 + o];
    }
    float mean = s * (1.f / (float)NPTS);
    float var  = s2 * (1.f / (float)NPTS) - mean * mean;
    g_stats[o] = mean;
    g_stats[256 + o] = rsqrtf(var + EPSBN);
}

// ---------------- k6: normalize (8 rows / block) -------------------------
__global__ void k6_norm(const float* __restrict__ bn_g,
                        const float* __restrict__ bn_b,
                        float* __restrict__ out) {
    int o = threadIdx.x;
    int p0 = blockIdx.x * 8;
    float mean = g_stats[o], inv = g_stats[256 + o];
    float g = __ldg(bn_g + o) * inv, b = __ldg(bn_b + o);
#pragma unroll
    for (int r = 0; r < 8; r++) {
        int idx = (p0 + r) * 256 + o;
        out[idx] = (g_pre[idx] - mean) * g + b;
    }
}

// ---------------- launch ---------------------------------------------------
extern "C" void kernel_launch(void* const* d_in, const int* in_sizes, int n_in,
                              void* d_out, int out_size) {
    const float* rep = (const float*)d_in[0];
    const float* pts = (const float*)d_in[1];
    const float* fts = (const float*)d_in[2];
    const float* d1w = (const float*)d_in[3];
    const float* d1b = (const float*)d_in[4];
    const float* d2w = (const float*)d_in[5];
    const float* d2b = (const float*)d_in[6];
    const float* cvw = (const float*)d_in[7];
    const float* cvb = (const float*)d_in[8];
    const float* x1w = (const float*)d_in[9];
    const float* x1b = (const float*)d_in[10];
    const float* x2w = (const float*)d_in[11];
    const float* x2b = (const float*)d_in[12];
    const float* dww = (const float*)d_in[13];
    const float* dwb = (const float*)d_in[14];
    const float* pww = (const float*)d_in[15];
    const float* bng = (const float*)d_in[16];
    const float* bnb = (const float*)d_in[17];
    float* out = (float*)d_out;

    k0_prep<<<128, 256>>>(cvw, pww);
    k1_lift<<<NPTS / 4, 128>>>(rep, pts, d1w, d1b, d2w, d2b);
    k2_xtrans<<<NPTS / K2P, 128>>>(cvb, x1w, x1b, x2w, x2b);
    k3_mid<<<NPTS / 8, 192>>>(fts, dww, dwb);
    k4_pw<<<NPTS / 64, 256>>>();
    k5_stats<<<1, 256>>>();
    k6_norm<<<NPTS / 8, 256>>>(bng, bnb, out);
}

// round 5
// speedup vs baseline: 1.0142x; 1.0142x over previous
#include <cuda_runtime.h>

// Problem constants
#define NPTS   16384           // N*P
#define KNB    16              // K neighbors
#define C_IN   128
#define C_MID  64
#define C_OUT  256
#define C_CAT  192             // C_MID + C_IN
#define KK     256             // K*K
#define CD     384             // C_CAT * DM
#define EPSBN  1e-5f

// ---------------- device scratch (no allocations allowed) ----------------
__device__ float g_pl  [NPTS * KNB * 3];     // pts_local
__device__ float g_lift[NPTS * KNB * C_MID]; // lifted features
__device__ float g_x   [NPTS * KK];          // X transform
__device__ float g_dw  [NPTS * CD];          // depthwise output
__device__ float g_pre [NPTS * C_OUT];       // pre-BN relu output
__device__ float g_cvt [48 * KK];            // cv_w transposed
__device__ float g_pwt [CD * C_OUT];         // pw_w transposed
__device__ float g_part[256 * 2 * C_OUT];    // per-block BN partials
__device__ float g_stats[2 * C_OUT];         // mean, inv_std

// ---------------- cp.async helpers ---------------------------------------
__device__ __forceinline__ unsigned su32(const void* p) {
    unsigned a;
    asm("{ .reg .u64 t; cvta.to.shared.u64 t, %1; cvt.u32.u64 %0, t; }"
        : "=r"(a) : "l"(p));
    return a;
}
__device__ __forceinline__ void cpa16(unsigned dst, const void* src) {
    asm volatile("cp.async.cg.shared.global [%0], [%1], 16;" :: "r"(dst), "l"(src));
}
#define CP_COMMIT() asm volatile("cp.async.commit_group;")

// ---------------- k0: transpose small weights ----------------------------
__global__ void k0_prep(const float* __restrict__ cv_w,
                        const float* __restrict__ pw_w) {
    int tot = 48 * KK + CD * C_OUT;
    for (int idx = blockIdx.x * blockDim.x + threadIdx.x; idx < tot;
         idx += gridDim.x * blockDim.x) {
        if (idx < 48 * KK) {
            int j = idx >> 8, o = idx & 255;
            int k = j / 3, d = j - k * 3;
            g_cvt[idx] = cv_w[o * 48 + d * 16 + k];
        } else {
            int i = idx - 48 * KK;
            int j = i >> 8, o = i & 255;
            g_pwt[i] = pw_w[o * CD + j];
        }
    }
}

// ---------------- k1: pts_local + lift MLP (3->64 relu ->64 relu) --------
// 8 points / block, 256 threads. rows = 8*16 = 128.
__global__ void k1_lift(const float* __restrict__ rep,
                        const float* __restrict__ pts,
                        const float* __restrict__ w1, const float* __restrict__ b1,
                        const float* __restrict__ w2, const float* __restrict__ b2) {
    __shared__ float s_pl[8 * KNB * 3];
    __shared__ float s_h[128 * C_MID];
    int tid = threadIdx.x;
    int base = blockIdx.x * 384;

    for (int idx = tid; idx < 384; idx += 256) {
        int p = blockIdx.x * 8 + idx / 48;
        int d = idx % 3;
        float v = pts[base + idx] - rep[p * 3 + d];
        s_pl[idx] = v;
        g_pl[base + idx] = v;
    }
    __syncthreads();

    for (int e = tid; e < 128 * 64; e += 256) {
        int row = e >> 6, o = e & 63;
        float v = __ldg(b1 + o);
        v += s_pl[row * 3 + 0] * __ldg(w1 + o);
        v += s_pl[row * 3 + 1] * __ldg(w1 + 64 + o);
        v += s_pl[row * 3 + 2] * __ldg(w1 + 128 + o);
        s_h[e] = fmaxf(v, 0.f);
    }
    __syncthreads();

    int cg = tid & 15, rg = tid >> 4;
    int r0 = rg * 8, c0 = cg * 4;
    float acc[8][4];
    float4 bb = __ldg((const float4*)(b2 + c0));
#pragma unroll
    for (int r = 0; r < 8; r++) {
        acc[r][0] = bb.x; acc[r][1] = bb.y; acc[r][2] = bb.z; acc[r][3] = bb.w;
    }
#pragma unroll 4
    for (int j = 0; j < 64; j++) {
        float4 w = __ldg((const float4*)(w2 + j * 64 + c0));
#pragma unroll
        for (int r = 0; r < 8; r++) {
            float a = s_h[(r0 + r) * 64 + j];
            acc[r][0] += a * w.x; acc[r][1] += a * w.y;
            acc[r][2] += a * w.z; acc[r][3] += a * w.w;
        }
    }
    int growbase = blockIdx.x * 128;
#pragma unroll
    for (int r = 0; r < 8; r++) {
        float4 v;
        v.x = fmaxf(acc[r][0], 0.f); v.y = fmaxf(acc[r][1], 0.f);
        v.z = fmaxf(acc[r][2], 0.f); v.w = fmaxf(acc[r][3], 0.f);
        *(float4*)(g_lift + (growbase + r0 + r) * 64 + c0) = v;
    }
}

// ---------------- k2: fused X-transform (48->256->256->256) --------------
// 16 points / block, 256 threads, tile 2 rows x 8 cols.
template <int KDIM, bool RELU, bool TOGLOBAL>
__device__ __forceinline__ void k2_stage(const float* sA,
                                         const float* __restrict__ W,
                                         const float* __restrict__ bias,
                                         float* sOut, float* gOut,
                                         int r0, int c0) {
    float acc[2][8];
    {
        float4 bb0 = __ldg((const float4*)(bias + c0));
        float4 bb1 = __ldg((const float4*)(bias + c0 + 4));
#pragma unroll
        for (int r = 0; r < 2; r++) {
            acc[r][0] = bb0.x; acc[r][1] = bb0.y; acc[r][2] = bb0.z; acc[r][3] = bb0.w;
            acc[r][4] = bb1.x; acc[r][5] = bb1.y; acc[r][6] = bb1.z; acc[r][7] = bb1.w;
        }
    }
#pragma unroll 8
    for (int j = 0; j < KDIM; j++) {
        float4 w0 = __ldg((const float4*)(W + j * 256 + c0));
        float4 w1 = __ldg((const float4*)(W + j * 256 + c0 + 4));
        float a0 = sA[(r0 + 0) * KDIM + j];
        float a1 = sA[(r0 + 1) * KDIM + j];
        acc[0][0] += a0 * w0.x; acc[0][1] += a0 * w0.y;
        acc[0][2] += a0 * w0.z; acc[0][3] += a0 * w0.w;
        acc[0][4] += a0 * w1.x; acc[0][5] += a0 * w1.y;
        acc[0][6] += a0 * w1.z; acc[0][7] += a0 * w1.w;
        acc[1][0] += a1 * w0.x; acc[1][1] += a1 * w0.y;
        acc[1][2] += a1 * w0.z; acc[1][3] += a1 * w0.w;
        acc[1][4] += a1 * w1.x; acc[1][5] += a1 * w1.y;
        acc[1][6] += a1 * w1.z; acc[1][7] += a1 * w1.w;
    }
#pragma unroll
    for (int r = 0; r < 2; r++) {
        float v[8];
#pragma unroll
        for (int t = 0; t < 8; t++)
            v[t] = RELU ? fmaxf(acc[r][t], 0.f) : acc[r][t];
        float* op = (TOGLOBAL ? gOut : sOut) + (r0 + r) * 256 + c0;
        *(float4*)op = make_float4(v[0], v[1], v[2], v[3]);
        *(float4*)(op + 4) = make_float4(v[4], v[5], v[6], v[7]);
    }
}

__global__ __launch_bounds__(256) void k2_xtrans(
        const float* __restrict__ cv_b,
        const float* __restrict__ x1w, const float* __restrict__ x1b,
        const float* __restrict__ x2w, const float* __restrict__ x2b) {
    __shared__ __align__(16) float s_a[16 * 48];    // 3KB
    __shared__ __align__(16) float s_x0[16 * KK];   // 16KB
    __shared__ __align__(16) float s_x1[16 * KK];   // 16KB
    int tid = threadIdx.x;
    int pbase = blockIdx.x * 16;

    for (int idx = tid; idx < 16 * 48; idx += 256)
        s_a[idx] = g_pl[pbase * 48 + idx];
    __syncthreads();

    int cg = tid & 31, rg = tid >> 5;   // 8 row-groups of 2, 32 col-groups of 8
    int r0 = rg * 2, c0 = cg * 8;

    k2_stage<48, true, false>(s_a, g_cvt, cv_b, s_x0, (float*)0, r0, c0);
    __syncthreads();
    k2_stage<256, true, false>(s_x0, x1w, x1b, s_x1, (float*)0, r0, c0);
    __syncthreads();
    k2_stage<256, false, true>(s_x1, x2w, x2b, (float*)0, g_x + pbase * KK, r0, c0);
}

// ---------------- k3: apply 16x16 X + depthwise conv ---------------------
// 8 points / block, 192 threads. cp.async double-buffered fcat + X prefetch.
__global__ __launch_bounds__(192) void k3_mid(const float* __restrict__ fts,
                                              const float* __restrict__ dww,
                                              const float* __restrict__ dwb) {
    __shared__ __align__(16) float s_mem[6656];   // 26 KB, multi-purpose
    int tid = threadIdx.x;

    // phase A: stage dw weights via padded transpose, hoist to registers
    for (int idx = tid; idx < 192 * 32; idx += 192) {
        int c = idx >> 5, i = idx & 31;
        s_mem[i * 193 + c] = dww[idx];
    }
    __syncthreads();
    float wreg[32];
#pragma unroll
    for (int i = 0; i < 32; i++) wreg[i] = s_mem[i * 193 + tid];
    float b0 = __ldg(dwb + 2 * tid), b1 = __ldg(dwb + 2 * tid + 1);
    __syncthreads();

    // phase B: reuse s_mem as double-buffered fcat (2x3072) + X (2x256)
    float* fb0 = s_mem;            float* fb1 = s_mem + 3072;
    float* xb0 = s_mem + 6144;     float* xb1 = s_mem + 6400;
    unsigned fbu[2] = { su32(fb0), su32(fb1) };
    unsigned xbu[2] = { su32(xb0), su32(xb1) };
    const float* fbp[2] = { fb0, fb1 };
    const float* xbp[2] = { xb0, xb1 };
    int p0 = blockIdx.x * 8;

#define K3_ISSUE(pp, buf)                                                     \
    {                                                                         \
        int p_ = p0 + (pp);                                                   \
        _Pragma("unroll")                                                     \
        for (int q = 0; q < 4; q++) {                                         \
            int chunk = q * 192 + tid;                                        \
            int j_ = chunk / 48, w_ = chunk % 48;                             \
            if (w_ < 16)                                                      \
                cpa16(fbu[buf] + (j_ * 192 + w_ * 4) * 4,                     \
                      g_lift + (p_ * 16 + j_) * 64 + w_ * 4);                 \
            else                                                              \
                cpa16(fbu[buf] + (j_ * 192 + 64 + (w_ - 16) * 4) * 4,         \
                      fts + (p_ * 16 + j_) * 128 + (w_ - 16) * 4);            \
        }                                                                     \
        if (tid < 64) cpa16(xbu[buf] + tid * 16, g_x + p_ * 256 + tid * 4);   \
    }

    K3_ISSUE(0, 0);
    CP_COMMIT();

    for (int pp = 0; pp < 8; pp++) {
        int cur = pp & 1;
        if (pp < 7) {
            K3_ISSUE(pp + 1, 1 - cur);
            CP_COMMIT();
            asm volatile("cp.async.wait_group 1;");
        } else {
            asm volatile("cp.async.wait_group 0;");
        }
        __syncthreads();

        float fcat[KNB];
#pragma unroll
        for (int j = 0; j < KNB; j++) fcat[j] = fbp[cur][j * 192 + tid];

        float fx[KNB];
        const float4* X4 = (const float4*)xbp[cur];
#pragma unroll
        for (int i = 0; i < KNB; i++) {
            float s = 0.f;
#pragma unroll
            for (int q = 0; q < 4; q++) {
                float4 x = X4[i * 4 + q];
                s += x.x * fcat[4 * q + 0] + x.y * fcat[4 * q + 1]
                   + x.z * fcat[4 * q + 2] + x.w * fcat[4 * q + 3];
            }
            fx[i] = s;
        }
        float a0 = b0, a1 = b1;
#pragma unroll
        for (int k = 0; k < KNB; k++) {
            a0 += fx[k] * wreg[k];
            a1 += fx[k] * wreg[16 + k];
        }
        int p = p0 + pp;
        *(float2*)(g_dw + p * CD + 2 * tid) = make_float2(a0, a1);
        __syncthreads();
    }
#undef K3_ISSUE
}

// ---------------- k4: pointwise GEMM 16384x384x256 + relu + BN partials --
__global__ __launch_bounds__(256) void k4_pw() {
    __shared__ float s_a[64 * 64];
    __shared__ float s_red[2 * 8 * C_OUT];
    int tid = threadIdx.x;
    int cg = tid & 31, rg = tid >> 5;
    int r0 = rg * 8, c0 = cg * 8;
    int rowbase = blockIdx.x * 64;

    float acc[8][8];
#pragma unroll
    for (int r = 0; r < 8; r++)
#pragma unroll
        for (int c = 0; c < 8; c++) acc[r][c] = 0.f;

    for (int jc = 0; jc < 6; jc++) {
        __syncthreads();
        for (int idx = tid; idx < 4096; idx += 256) {
            int r = idx >> 6, j = idx & 63;
            s_a[idx] = g_dw[(rowbase + r) * CD + jc * 64 + j];
        }
        __syncthreads();
#pragma unroll 4
        for (int j = 0; j < 64; j++) {
            const float* wp = g_pwt + (jc * 64 + j) * 256 + c0;
            float4 w0 = __ldg((const float4*)wp);
            float4 w1 = __ldg((const float4*)(wp + 4));
#pragma unroll
            for (int r = 0; r < 8; r++) {
                float a = s_a[(r0 + r) * 64 + j];
                acc[r][0] += a * w0.x; acc[r][1] += a * w0.y;
                acc[r][2] += a * w0.z; acc[r][3] += a * w0.w;
                acc[r][4] += a * w1.x; acc[r][5] += a * w1.y;
                acc[r][6] += a * w1.z; acc[r][7] += a * w1.w;
            }
        }
    }

    float csum[8], csq[8];
#pragma unroll
    for (int c = 0; c < 8; c++) { csum[c] = 0.f; csq[c] = 0.f; }
#pragma unroll
    for (int r = 0; r < 8; r++) {
#pragma unroll
        for (int c = 0; c < 8; c++) {
            float v = fmaxf(acc[r][c], 0.f);
            acc[r][c] = v;
            csum[c] += v; csq[c] += v * v;
        }
        float4 v0 = make_float4(acc[r][0], acc[r][1], acc[r][2], acc[r][3]);
        float4 v1 = make_float4(acc[r][4], acc[r][5], acc[r][6], acc[r][7]);
        float* op = g_pre + (rowbase + r0 + r) * C_OUT + c0;
        *(float4*)op = v0;
        *(float4*)(op + 4) = v1;
    }
#pragma unroll
    for (int c = 0; c < 8; c++) {
        s_red[rg * C_OUT + c0 + c] = csum[c];
        s_red[8 * C_OUT + rg * C_OUT + c0 + c] = csq[c];
    }
    __syncthreads();
    float s = 0.f, s2 = 0.f;
#pragma unroll
    for (int g = 0; g < 8; g++) {
        s  += s_red[g * C_OUT + tid];
        s2 += s_red[8 * C_OUT + g * C_OUT + tid];
    }
    g_part[blockIdx.x * 512 + tid] = s;
    g_part[blockIdx.x * 512 + 256 + tid] = s2;
}

// ---------------- k5: final BN stats -------------------------------------
__global__ void k5_stats() {
    int o = threadIdx.x;
    float s = 0.f, s2 = 0.f;
    for (int b = 0; b < 256; b++) {
        s  += g_part[b * 512 + o];
        s2 += g_part[b * 512 + 256 + o];
    }
    float mean = s * (1.f / (float)NPTS);
    float var  = s2 * (1.f / (float)NPTS) - mean * mean;
    g_stats[o] = mean;
    g_stats[256 + o] = rsqrtf(var + EPSBN);
}

// ---------------- k6: normalize (8 rows / block) -------------------------
__global__ void k6_norm(const float* __restrict__ bn_g,
                        const float* __restrict__ bn_b,
                        float* __restrict__ out) {
    int o = threadIdx.x;
    int p0 = blockIdx.x * 8;
    float mean = g_stats[o], inv = g_stats[256 + o];
    float g = __ldg(bn_g + o) * inv, b = __ldg(bn_b + o);
#pragma unroll
    for (int r = 0; r < 8; r++) {
        int idx = (p0 + r) * 256 + o;
        out[idx] = (g_pre[idx] - mean) * g + b;
    }
}

// ---------------- launch ---------------------------------------------------
extern "C" void kernel_launch(void* const* d_in, const int* in_sizes, int n_in,
                              void* d_out, int out_size) {
    const float* rep = (const float*)d_in[0];
    const float* pts = (const float*)d_in[1];
    const float* fts = (const float*)d_in[2];
    const float* d1w = (const float*)d_in[3];
    const float* d1b = (const float*)d_in[4];
    const float* d2w = (const float*)d_in[5];
    const float* d2b = (const float*)d_in[6];
    const float* cvw = (const float*)d_in[7];
    const float* cvb = (const float*)d_in[8];
    const float* x1w = (const float*)d_in[9];
    const float* x1b = (const float*)d_in[10];
    const float* x2w = (const float*)d_in[11];
    const float* x2b = (const float*)d_in[12];
    const float* dww = (const float*)d_in[13];
    const float* dwb = (const float*)d_in[14];
    const float* pww = (const float*)d_in[15];
    const float* bng = (const float*)d_in[16];
    const float* bnb = (const float*)d_in[17];
    float* out = (float*)d_out;

    k0_prep<<<128, 256>>>(cvw, pww);
    k1_lift<<<NPTS / 8, 256>>>(rep, pts, d1w, d1b, d2w, d2b);
    k2_xtrans<<<NPTS / 16, 256>>>(cvb, x1w, x1b, x2w, x2b);
    k3_mid<<<NPTS / 8, 192>>>(fts, dww, dwb);
    k4_pw<<<NPTS / 64, 256>>>();
    k5_stats<<<1, 256>>>();
    k6_norm<<<NPTS / 8, 256>>>(bng, bnb, out);
}

// round 6
// speedup vs baseline: 1.6484x; 1.6252x over previous
#include <cuda_runtime.h>

// Problem constants
#define NPTS   16384           // N*P
#define KNB    16              // K neighbors
#define C_IN   128
#define C_MID  64
#define C_OUT  256
#define C_CAT  192             // C_MID + C_IN
#define KK     256             // K*K
#define CD     384             // C_CAT * DM
#define EPSBN  1e-5f

// ---------------- device scratch (no allocations allowed) ----------------
__device__ float g_pl  [NPTS * KNB * 3];     // pts_local
__device__ float g_lift[NPTS * KNB * C_MID]; // lifted features
__device__ float g_x   [NPTS * KK];          // X transform
__device__ float g_dw  [NPTS * CD];          // depthwise output
__device__ float g_pre [NPTS * C_OUT];       // pre-BN relu output
__device__ float g_part[128 * 512];          // per-block BN partials (k4 layout)
__device__ float g_stats[2 * C_OUT];         // mean, inv_std
// fragment-packed tf32 hi/lo weights: quad = [hi0, hi1, lo0, lo1]
__device__ float g_p1[6  * 32 * 32 * 4];     // cv  (K=48)
__device__ float g_p2[32 * 32 * 32 * 4];     // x1  (K=256)
__device__ float g_p3[32 * 32 * 32 * 4];     // x2  (K=256)
__device__ float g_p4[48 * 32 * 32 * 4];     // pw  (K=384, B[j][o]=pw[o][j])

// ---------------- tf32 / mma helpers -------------------------------------
__device__ __forceinline__ unsigned tf32of(float x) {
    unsigned r;
    asm("cvt.rna.tf32.f32 %0, %1;" : "=r"(r) : "f"(x));
    return r;
}
__device__ __forceinline__ void mma8(float* d, unsigned a0, unsigned a1,
                                     unsigned a2, unsigned a3,
                                     unsigned b0, unsigned b1) {
    asm volatile(
        "mma.sync.aligned.m16n8k8.row.col.f32.tf32.tf32.f32 "
        "{%0,%1,%2,%3}, {%4,%5,%6,%7}, {%8,%9}, {%0,%1,%2,%3};"
        : "+f"(d[0]), "+f"(d[1]), "+f"(d[2]), "+f"(d[3])
        : "r"(a0), "r"(a1), "r"(a2), "r"(a3), "r"(b0), "r"(b1));
}

// ---------------- k0: pack tf32 hi/lo weight fragments -------------------
// quad index -> (ks, nt, lane); b0 = B[ks*8+tig][nt*8+gid], b1 = +4 row.
__global__ void k0_prep(const float* __restrict__ cvw,
                        const float* __restrict__ x1w,
                        const float* __restrict__ x2w,
                        const float* __restrict__ pww) {
    const int nq1 = 6 * 1024, nq2 = 32 * 1024, nq3 = 32 * 1024, nq4 = 48 * 1024;
    int tot = nq1 + nq2 + nq3 + nq4;
    for (int idx = blockIdx.x * blockDim.x + threadIdx.x; idx < tot;
         idx += gridDim.x * blockDim.x) {
        int l, mtx;
        if (idx < nq1)              { l = idx;              mtx = 1; }
        else if (idx < nq1+nq2)     { l = idx - nq1;        mtx = 2; }
        else if (idx < nq1+nq2+nq3) { l = idx - nq1 - nq2;  mtx = 3; }
        else                        { l = idx - nq1-nq2-nq3; mtx = 4; }
        int lane = l & 31, nt = (l >> 5) & 31, ks = l >> 10;
        int gid = lane >> 2, tig = lane & 3;
        int k0e = ks * 8 + tig, k1e = k0e + 4;
        int n = nt * 8 + gid;
        float b0, b1; float* dst;
        if (mtx == 1) {
            b0 = cvw[n * 48 + (k0e % 3) * 16 + k0e / 3];
            b1 = cvw[n * 48 + (k1e % 3) * 16 + k1e / 3];
            dst = g_p1 + l * 4;
        } else if (mtx == 2) {
            b0 = x1w[k0e * 256 + n];  b1 = x1w[k1e * 256 + n];
            dst = g_p2 + l * 4;
        } else if (mtx == 3) {
            b0 = x2w[k0e * 256 + n];  b1 = x2w[k1e * 256 + n];
            dst = g_p3 + l * 4;
        } else {
            b0 = pww[n * CD + k0e];   b1 = pww[n * CD + k1e];
            dst = g_p4 + l * 4;
        }
        unsigned h0 = tf32of(b0), h1 = tf32of(b1);
        float h0f = __uint_as_float(h0), h1f = __uint_as_float(h1);
        unsigned l0 = tf32of(b0 - h0f), l1 = tf32of(b1 - h1f);
        float4 q = make_float4(h0f, h1f, __uint_as_float(l0), __uint_as_float(l1));
        *(float4*)dst = q;
    }
}

// ---------------- k1: pts_local + lift MLP (3->64 relu ->64 relu) --------
// 8 points / block, 256 threads. rows = 8*16 = 128.
__global__ void k1_lift(const float* __restrict__ rep,
                        const float* __restrict__ pts,
                        const float* __restrict__ w1, const float* __restrict__ b1,
                        const float* __restrict__ w2, const float* __restrict__ b2) {
    __shared__ float s_pl[8 * KNB * 3];
    __shared__ float s_h[128 * C_MID];
    int tid = threadIdx.x;
    int base = blockIdx.x * 384;

    for (int idx = tid; idx < 384; idx += 256) {
        int p = blockIdx.x * 8 + idx / 48;
        int d = idx % 3;
        float v = pts[base + idx] - rep[p * 3 + d];
        s_pl[idx] = v;
        g_pl[base + idx] = v;
    }
    __syncthreads();

    for (int e = tid; e < 128 * 64; e += 256) {
        int row = e >> 6, o = e & 63;
        float v = __ldg(b1 + o);
        v += s_pl[row * 3 + 0] * __ldg(w1 + o);
        v += s_pl[row * 3 + 1] * __ldg(w1 + 64 + o);
        v += s_pl[row * 3 + 2] * __ldg(w1 + 128 + o);
        s_h[e] = fmaxf(v, 0.f);
    }
    __syncthreads();

    int cg = tid & 15, rg = tid >> 4;
    int r0 = rg * 8, c0 = cg * 4;
    float acc[8][4];
    float4 bb = __ldg((const float4*)(b2 + c0));
#pragma unroll
    for (int r = 0; r < 8; r++) {
        acc[r][0] = bb.x; acc[r][1] = bb.y; acc[r][2] = bb.z; acc[r][3] = bb.w;
    }
#pragma unroll 4
    for (int j = 0; j < 64; j++) {
        float4 w = __ldg((const float4*)(w2 + j * 64 + c0));
#pragma unroll
        for (int r = 0; r < 8; r++) {
            float a = s_h[(r0 + r) * 64 + j];
            acc[r][0] += a * w.x; acc[r][1] += a * w.y;
            acc[r][2] += a * w.z; acc[r][3] += a * w.w;
        }
    }
    int growbase = blockIdx.x * 128;
#pragma unroll
    for (int r = 0; r < 8; r++) {
        float4 v;
        v.x = fmaxf(acc[r][0], 0.f); v.y = fmaxf(acc[r][1], 0.f);
        v.z = fmaxf(acc[r][2], 0.f); v.w = fmaxf(acc[r][3], 0.f);
        *(float4*)(g_lift + (growbase + r0 + r) * 64 + c0) = v;
    }
}

// ---------------- k2: fused X-transform via 3xTF32 mma.sync --------------
// 16 points/block, 256 threads = 8 warps; each warp: M=16 rows x N=32 (4 nt).
// Stages: K=48 (6 ks) -> relu -> K=256 (32 ks) -> relu -> K=256 -> g_x.
#define LDA1 52
#define LDAB 260

template<int NKS, int LDA, bool RELU, bool TOG>
__device__ __forceinline__ void mma_stage(const float* sA,
                                          const float* __restrict__ Bp,
                                          const float* __restrict__ bias,
                                          float* sOut, float* gOut,
                                          int n0, int gid, int tig, int lane) {
    float acc[4][4];
#pragma unroll
    for (int nt = 0; nt < 4; nt++)
#pragma unroll
        for (int t = 0; t < 4; t++) acc[nt][t] = 0.f;

#pragma unroll 2
    for (int ks = 0; ks < NKS; ks++) {
        const float* ar0 = sA + gid * LDA + ks * 8;
        const float* ar1 = sA + (gid + 8) * LDA + ks * 8;
        float x0 = ar0[tig], x1 = ar1[tig];
        float x2 = ar0[tig + 4], x3 = ar1[tig + 4];
        unsigned ah0 = tf32of(x0), ah1 = tf32of(x1);
        unsigned ah2 = tf32of(x2), ah3 = tf32of(x3);
        unsigned al0 = tf32of(x0 - __uint_as_float(ah0));
        unsigned al1 = tf32of(x1 - __uint_as_float(ah1));
        unsigned al2 = tf32of(x2 - __uint_as_float(ah2));
        unsigned al3 = tf32of(x3 - __uint_as_float(ah3));
#pragma unroll
        for (int nt = 0; nt < 4; nt++) {
            int ntg = (n0 >> 3) + nt;
            uint4 B = *(const uint4*)(Bp + ((ks * 32 + ntg) * 32 + lane) * 4);
            mma8(acc[nt], ah0, ah1, ah2, ah3, B.x, B.y);   // Ahi*Bhi
            mma8(acc[nt], al0, al1, al2, al3, B.x, B.y);   // Alo*Bhi
            mma8(acc[nt], ah0, ah1, ah2, ah3, B.z, B.w);   // Ahi*Blo
        }
    }
#pragma unroll
    for (int nt = 0; nt < 4; nt++) {
        int col = n0 + nt * 8 + 2 * tig;
        float2 bb = __ldg((const float2*)(bias + col));
        float v0 = acc[nt][0] + bb.x, v1 = acc[nt][1] + bb.y;
        float v2 = acc[nt][2] + bb.x, v3 = acc[nt][3] + bb.y;
        if (RELU) {
            v0 = fmaxf(v0, 0.f); v1 = fmaxf(v1, 0.f);
            v2 = fmaxf(v2, 0.f); v3 = fmaxf(v3, 0.f);
        }
        if (TOG) {
            *(float2*)(gOut + gid * 256 + col) = make_float2(v0, v1);
            *(float2*)(gOut + (gid + 8) * 256 + col) = make_float2(v2, v3);
        } else {
            *(float2*)(sOut + gid * LDAB + col) = make_float2(v0, v1);
            *(float2*)(sOut + (gid + 8) * LDAB + col) = make_float2(v2, v3);
        }
    }
}

__global__ __launch_bounds__(256) void k2_xtrans(
        const float* __restrict__ cv_b,
        const float* __restrict__ x1b,
        const float* __restrict__ x2b) {
    __shared__ float s_in[16 * LDA1];     // 3.3 KB
    __shared__ float bufA[16 * LDAB];     // 16.6 KB
    __shared__ float bufB[16 * LDAB];     // 16.6 KB
    int tid = threadIdx.x;
    int lane = tid & 31, w = tid >> 5;
    int gid = lane >> 2, tig = lane & 3;
    int n0 = w * 32;
    int pbase = blockIdx.x * 16;

    for (int idx = tid; idx < 16 * 48; idx += 256) {
        int row = idx / 48, c = idx - row * 48;
        s_in[row * LDA1 + c] = g_pl[pbase * 48 + idx];
    }
    __syncthreads();

    mma_stage<6, LDA1, true, false>(s_in, g_p1, cv_b, bufA, (float*)0,
                                    n0, gid, tig, lane);
    __syncthreads();
    mma_stage<32, LDAB, true, false>(bufA, g_p2, x1b, bufB, (float*)0,
                                     n0, gid, tig, lane);
    __syncthreads();
    mma_stage<32, LDAB, false, true>(bufB, g_p3, x2b, (float*)0,
                                     g_x + pbase * 256, n0, gid, tig, lane);
}

// ---------------- k3: apply 16x16 X + depthwise conv (R2 version) --------
__global__ void k3_mid(const float* __restrict__ fts,
                       const float* __restrict__ dww,
                       const float* __restrict__ dwb) {
    __shared__ float s_wt[32 * 193];
    __shared__ __align__(16) float s_X[KK];
    int tid = threadIdx.x;

    for (int idx = tid; idx < 192 * 32; idx += 192) {
        int c = idx >> 5, i = idx & 31;
        s_wt[i * 193 + c] = dww[idx];
    }
    __syncthreads();
    float wreg[32];
#pragma unroll
    for (int i = 0; i < 32; i++) wreg[i] = s_wt[i * 193 + tid];
    float b0 = __ldg(dwb + 2 * tid), b1 = __ldg(dwb + 2 * tid + 1);

    for (int pp = 0; pp < 8; pp++) {
        int p = blockIdx.x * 8 + pp;
        __syncthreads();
        for (int i = tid; i < KK; i += 192) s_X[i] = g_x[p * KK + i];
        __syncthreads();

        float fcat[KNB];
        if (tid < C_MID) {
#pragma unroll
            for (int j = 0; j < KNB; j++)
                fcat[j] = g_lift[(p * KNB + j) * C_MID + tid];
        } else {
            int cc = tid - C_MID;
#pragma unroll
            for (int j = 0; j < KNB; j++)
                fcat[j] = __ldg(fts + (p * KNB + j) * C_IN + cc);
        }

        float fx[KNB];
        const float4* X4 = (const float4*)s_X;
#pragma unroll
        for (int i = 0; i < KNB; i++) {
            float s = 0.f;
#pragma unroll
            for (int q = 0; q < 4; q++) {
                float4 x = X4[i * 4 + q];
                s += x.x * fcat[q * 4 + 0] + x.y * fcat[q * 4 + 1]
                   + x.z * fcat[q * 4 + 2] + x.w * fcat[q * 4 + 3];
            }
            fx[i] = s;
        }
        float a0 = b0, a1 = b1;
#pragma unroll
        for (int k = 0; k < KNB; k++) {
            a0 += fx[k] * wreg[k];
            a1 += fx[k] * wreg[16 + k];
        }
        *(float2*)(g_dw + p * CD + 2 * tid) = make_float2(a0, a1);
    }
}

// ---------------- k4: pointwise GEMM via 3xTF32 mma + relu + BN ----------
// grid (128, 2): block = 128 rows x 128 cols. 256 threads = 8 m-warps.
#define LDA4 36
__global__ __launch_bounds__(256) void k4_pw() {
    __shared__ float s_a[128 * LDA4];     // 18 KB (reused for BN reduce)
    int tid = threadIdx.x;
    int lane = tid & 31, w = tid >> 5;
    int gid = lane >> 2, tig = lane & 3;
    int rb = blockIdx.x * 128;
    int by = blockIdx.y;

    float acc[16][4];
#pragma unroll
    for (int nt = 0; nt < 16; nt++)
#pragma unroll
        for (int t = 0; t < 4; t++) acc[nt][t] = 0.f;

    for (int kc = 0; kc < 12; kc++) {
        __syncthreads();
        for (int idx = tid; idx < 1024; idx += 256) {
            int row = idx >> 3, q = idx & 7;
            float4 v = *(const float4*)(g_dw + (rb + row) * CD + kc * 32 + q * 4);
            *(float4*)(s_a + row * LDA4 + q * 4) = v;
        }
        __syncthreads();
#pragma unroll
        for (int ksl = 0; ksl < 4; ksl++) {
            int ks = kc * 4 + ksl;
            const float* ar0 = s_a + (w * 16 + gid) * LDA4 + ksl * 8;
            const float* ar1 = s_a + (w * 16 + gid + 8) * LDA4 + ksl * 8;
            float x0 = ar0[tig], x1 = ar1[tig];
            float x2 = ar0[tig + 4], x3 = ar1[tig + 4];
            unsigned ah0 = tf32of(x0), ah1 = tf32of(x1);
            unsigned ah2 = tf32of(x2), ah3 = tf32of(x3);
            unsigned al0 = tf32of(x0 - __uint_as_float(ah0));
            unsigned al1 = tf32of(x1 - __uint_as_float(ah1));
            unsigned al2 = tf32of(x2 - __uint_as_float(ah2));
            unsigned al3 = tf32of(x3 - __uint_as_float(ah3));
#pragma unroll
            for (int nt = 0; nt < 16; nt++) {
                int ntg = by * 16 + nt;
                uint4 B = *(const uint4*)(g_p4 + ((ks * 32 + ntg) * 32 + lane) * 4);
                mma8(acc[nt], ah0, ah1, ah2, ah3, B.x, B.y);
                mma8(acc[nt], al0, al1, al2, al3, B.x, B.y);
                mma8(acc[nt], ah0, ah1, ah2, ah3, B.z, B.w);
            }
        }
    }

    // epilogue: relu, store, deterministic BN partials
    __syncthreads();
    float* s_red = s_a;    // 8 warps * 128 cols sums + 1024-off squares
    int r0 = rb + w * 16 + gid, r1 = r0 + 8;
#pragma unroll
    for (int nt = 0; nt < 16; nt++) {
        int col = nt * 8 + 2 * tig;
        float v0 = fmaxf(acc[nt][0], 0.f), v1 = fmaxf(acc[nt][1], 0.f);
        float v2 = fmaxf(acc[nt][2], 0.f), v3 = fmaxf(acc[nt][3], 0.f);
        *(float2*)(g_pre + r0 * 256 + by * 128 + col) = make_float2(v0, v1);
        *(float2*)(g_pre + r1 * 256 + by * 128 + col) = make_float2(v2, v3);
        float s0 = v0 + v2, s1 = v1 + v3;
        float q0 = v0 * v0 + v2 * v2, q1 = v1 * v1 + v3 * v3;
#pragma unroll
        for (int m = 4; m < 32; m <<= 1) {
            s0 += __shfl_xor_sync(0xffffffffu, s0, m);
            s1 += __shfl_xor_sync(0xffffffffu, s1, m);
            q0 += __shfl_xor_sync(0xffffffffu, q0, m);
            q1 += __shfl_xor_sync(0xffffffffu, q1, m);
        }
        if (gid == 0) {
            s_red[w * 128 + col] = s0;
            s_red[w * 128 + col + 1] = s1;
            s_red[1024 + w * 128 + col] = q0;
            s_red[1024 + w * 128 + col + 1] = q1;
        }
    }
    __syncthreads();
    if (tid < 128) {
        float s = 0.f, s2 = 0.f;
#pragma unroll
        for (int wq = 0; wq < 8; wq++) {
            s  += s_red[wq * 128 + tid];
            s2 += s_red[1024 + wq * 128 + tid];
        }
        g_part[blockIdx.x * 512 + by * 256 + tid] = s;
        g_part[blockIdx.x * 512 + by * 256 + 128 + tid] = s2;
    }
}

// ---------------- k5: final BN stats -------------------------------------
__global__ void k5_stats() {
    int o = threadIdx.x;
    int by = o >> 7, oc = o & 127;
    float s = 0.f, s2 = 0.f;
    for (int bx = 0; bx < 128; bx++) {
        s  += g_part[bx * 512 + by * 256 + oc];
        s2 += g_part[bx * 512 + by * 256 + 128 + oc];
    }
    float mean = s * (1.f / (float)NPTS);
    float var  = s2 * (1.f / (float)NPTS) - mean * mean;
    g_stats[o] = mean;
    g_stats[256 + o] = rsqrtf(var + EPSBN);
}

// ---------------- k6: normalize (8 rows / block) -------------------------
__global__ void k6_norm(const float* __restrict__ bn_g,
                        const float* __restrict__ bn_b,
                        float* __restrict__ out) {
    int o = threadIdx.x;
    int p0 = blockIdx.x * 8;
    float mean = g_stats[o], inv = g_stats[256 + o];
    float g = __ldg(bn_g + o) * inv, b = __ldg(bn_b + o);
#pragma unroll
    for (int r = 0; r < 8; r++) {
        int idx = (p0 + r) * 256 + o;
        out[idx] = (g_pre[idx] - mean) * g + b;
    }
}

// ---------------- launch ---------------------------------------------------
extern "C" void kernel_launch(void* const* d_in, const int* in_sizes, int n_in,
                              void* d_out, int out_size) {
    const float* rep = (const float*)d_in[0];
    const float* pts = (const float*)d_in[1];
    const float* fts = (const float*)d_in[2];
    const float* d1w = (const float*)d_in[3];
    const float* d1b = (const float*)d_in[4];
    const float* d2w = (const float*)d_in[5];
    const float* d2b = (const float*)d_in[6];
    const float* cvw = (const float*)d_in[7];
    const float* cvb = (const float*)d_in[8];
    const float* x1w = (const float*)d_in[9];
    const float* x1b = (const float*)d_in[10];
    const float* x2w = (const float*)d_in[11];
    const float* x2b = (const float*)d_in[12];
    const float* dww = (const float*)d_in[13];
    const float* dwb = (const float*)d_in[14];
    const float* pww = (const float*)d_in[15];
    const float* bng = (const float*)d_in[16];
    const float* bnb = (const float*)d_in[17];
    float* out = (float*)d_out;

    k0_prep<<<256, 256>>>(cvw, x1w, x2w, pww);
    k1_lift<<<NPTS / 8, 256>>>(rep, pts, d1w, d1b, d2w, d2b);
    k2_xtrans<<<NPTS / 16, 256>>>(cvb, x1b, x2b);
    k3_mid<<<NPTS / 8, 192>>>(fts, dww, dwb);
    k4_pw<<<dim3(128, 2), 256>>>();
    k5_stats<<<1, 256>>>();
    k6_norm<<<NPTS / 8, 256>>>(bng, bnb, out);
}